// round 2
// baseline (speedup 1.0000x reference)
#include <cuda_runtime.h>
#include <cuda_bf16.h>
#include <math.h>

// HierarchicalDistanceLoss:
//   ce[b]  = logsumexp(logits[b,:]) - logits[b, labels[b]]
//   pred   = argmax(logits[b,:]) (first max)
//   df[b]  = dis_matrix[labels[b], pred] + 0.5
//   out[0] = mean(ce*df), out[1..B] = df
//
// HBM-bound: stage logits through smem with padded rows (11 float4 = 44 floats)
// so global loads are perfectly coalesced and smem row reads are LDS.128
// conflict-free (stride 11 float4 -> a4 mod 8 distinct per 8-lane phase).

#define CCOLS 40
#define RPB   256            // rows per block == threads per block
#define F4_PER_ROW 10        // 40 floats
#define PAD_F4     11        // padded row length in float4

__device__ float g_partials[8192];   // per-block loss partials (scratch, no alloc)

__global__ void __launch_bounds__(RPB) hier_loss_main(
    const float4* __restrict__ logits4,   // [B*10] float4
    const int*    __restrict__ labels,    // [B]
    const float*  __restrict__ dis,       // [40*40]
    float*        __restrict__ df_out)    // [B]
{
    __shared__ float4 tile[RPB * PAD_F4];   // 45056 B
    __shared__ float  wsum[8];

    const int tid = threadIdx.x;
    const long long blk = blockIdx.x;

    // ---- coalesced global load -> padded smem ----
    const float4* g = logits4 + blk * (RPB * F4_PER_ROW);
    #pragma unroll
    for (int it = 0; it < F4_PER_ROW; ++it) {
        int idx = it * RPB + tid;            // 0..2559, consecutive per warp
        int row = idx / F4_PER_ROW;
        int s   = idx - row * F4_PER_ROW;
        tile[row * PAD_F4 + s] = g[idx];
    }
    __syncthreads();

    // ---- each thread processes its own row from smem ----
    const float4* r = tile + tid * PAD_F4;
    const float*  rf = (const float*)r;

    // pass 1: max + argmax (strict > keeps first occurrence, matches jnp.argmax)
    float m = -INFINITY;
    int   am = 0;
    #pragma unroll
    for (int i = 0; i < F4_PER_ROW; ++i) {
        float4 v = r[i];
        if (v.x > m) { m = v.x; am = 4*i;   }
        if (v.y > m) { m = v.y; am = 4*i+1; }
        if (v.z > m) { m = v.z; am = 4*i+2; }
        if (v.w > m) { m = v.w; am = 4*i+3; }
    }

    // pass 2: sum of exp(x - m)
    float s = 0.0f;
    #pragma unroll
    for (int i = 0; i < F4_PER_ROW; ++i) {
        float4 v = r[i];
        s += __expf(v.x - m) + __expf(v.y - m) + __expf(v.z - m) + __expf(v.w - m);
    }
    float lse = m + __logf(s);

    const long long rowg = blk * RPB + tid;
    const int lab = labels[rowg];
    const float xl = rf[lab];
    const float ce = lse - xl;

    const float dfv = __ldg(&dis[lab * CCOLS + am]) + 0.5f;
    df_out[rowg] = dfv;

    // ---- block reduction of ce*df (deterministic tree) ----
    float c = ce * dfv;
    #pragma unroll
    for (int o = 16; o > 0; o >>= 1)
        c += __shfl_down_sync(0xffffffffu, c, o);
    if ((tid & 31) == 0) wsum[tid >> 5] = c;
    __syncthreads();
    if (tid < 32) {
        float v = (tid < 8) ? wsum[tid] : 0.0f;
        #pragma unroll
        for (int o = 4; o > 0; o >>= 1)
            v += __shfl_down_sync(0xffffffffu, v, o);
        if (tid == 0) g_partials[blockIdx.x] = v;
    }
}

__global__ void __launch_bounds__(256) hier_loss_finish(
    float* __restrict__ out, float invB, int nblocks)
{
    __shared__ float wsum[8];
    const int tid = threadIdx.x;
    float s = 0.0f;
    for (int i = tid; i < nblocks; i += 256)
        s += g_partials[i];
    #pragma unroll
    for (int o = 16; o > 0; o >>= 1)
        s += __shfl_down_sync(0xffffffffu, s, o);
    if ((tid & 31) == 0) wsum[tid >> 5] = s;
    __syncthreads();
    if (tid < 32) {
        float v = (tid < 8) ? wsum[tid] : 0.0f;
        #pragma unroll
        for (int o = 4; o > 0; o >>= 1)
            v += __shfl_down_sync(0xffffffffu, v, o);
        if (tid == 0) out[0] = v * invB;   // mean, NORMALISE = 1
    }
}

extern "C" void kernel_launch(void* const* d_in, const int* in_sizes, int n_in,
                              void* d_out, int out_size)
{
    const float* logits = (const float*)d_in[0];
    const int*   labels = (const int*)d_in[1];
    const float* dis    = (const float*)d_in[2];
    float* out = (float*)d_out;

    const long long B = (long long)in_sizes[1];     // 1048576
    const int nb = (int)(B / RPB);                  // 4096 (B divisible by 256)

    // output layout: [loss, df[0..B-1]] if out_size == B+1, else just df
    const int off = out_size - (int)B;
    float* dfo = out + (off > 0 ? off : 0);

    hier_loss_main<<<nb, RPB>>>((const float4*)logits, labels, dis, dfo);
    if (off > 0)
        hier_loss_finish<<<1, 256>>>(out, 1.0f / (float)B, nb);
}